// round 11
// baseline (speedup 1.0000x reference)
#include <cuda_runtime.h>

#define NB 32
#define NPTS 512
#define NC 64
#define PIX (NC * NC)          // 4096
#define ROWS (NPTS + 1)        // 513
#define INV2S2 0.0078125f      // 1/(2*8^2)
#define BG_RATIO 0.15f

// ---------------------------------------------------------------------------
// Single fused kernel. CTA = (batch b, chain c): tile0 = i rows [16c,16c+8),
// tile1 = [16c+8,16c+16). 256 threads.
//
// Build: thread t computes rows n = t, t+256 of
//   sEx[n][j]  = exp(-(x^2-2xc_j+c_j^2)/128)  (64 cols)
//   sEy0/1[n][k] = same in y at cols i0..i0+7 / i0+8..i0+15
// directly from points[b] + cood. No global scratch, no second kernel.
//
// A (exposed, DRAM idle -> minimize): tile0 reduce with 4-way n-split:
//   thread (q, ia, j8) reduces n in [128q,128q+128) for 8 j, partials to smem,
//   then combine in (iloc, jp) layout.  ~4x faster than a flat 512-iter loop.
// B: store tile0 row n AND accumulate tile1 (shared ex load) - reduce hidden.
// C: finalize tile1; store tile1 rows.
// Softmax identity: out = Ey*Ex/(S+ebg); bg = ebg/(S+ebg);
// min_dis = max(0, -128 ln(max_n Ey*Ex)). Exact quotient, no max-shift.
// ---------------------------------------------------------------------------
#define SMEM_FLOATS (NPTS * NC + NPTS * 16 + NC + 4096)
#define SMEM_BYTES  (SMEM_FLOATS * 4)               // 180480

__global__ __launch_bounds__(256, 1)
void post_prob_kernel(const float* __restrict__ points,
                      const float* __restrict__ st_sizes,
                      const float* __restrict__ cood,
                      float* __restrict__ out) {
    extern __shared__ float smem[];
    float* sEx   = smem;                   // [512][64]
    float* sEy0  = smem + NPTS * NC;       // [512][8]
    float* sEy1  = sEy0 + NPTS * 8;        // [512][8]
    float* sCood = sEy1 + NPTS * 8;        // [64]
    float* sPS   = sCood + NC;             // [4][8][64] partial sums
    float* sPM   = sPS + 2048;             // [4][8][64] partial maxes

    int b  = blockIdx.x >> 2;
    int c  = blockIdx.x & 3;
    int i0 = c << 4;                       // tile0 base; tile1 = i0+8
    int t  = threadIdx.x;
    int iloc = t >> 5;                     // warp id (0..7) = row in tile
    int jp   = t & 31;                     // j pair index

    if (t < NC) sCood[t] = cood[t];
    __syncthreads();

    // ---- build phase ----
#pragma unroll
    for (int r = 0; r < 2; r++) {
        int n = t + (r << 8);
        float2 pt = *(const float2*)(points + ((size_t)b * NPTS + n) * 2);
        float x = pt.x, y = pt.y;
        float x2 = x * x, y2 = y * y;
        float tx = 2.0f * x, ty = 2.0f * y;

#pragma unroll
        for (int q = 0; q < 16; q++) {
            int jb = ((q + t) & 15) << 2;
            float4 cv = *(const float4*)&sCood[jb];
            float4 e;
            e.x = __expf(-(x2 - tx * cv.x + cv.x * cv.x) * INV2S2);
            e.y = __expf(-(x2 - tx * cv.y + cv.y * cv.y) * INV2S2);
            e.z = __expf(-(x2 - tx * cv.z + cv.z * cv.z) * INV2S2);
            e.w = __expf(-(x2 - tx * cv.w + cv.w * cv.w) * INV2S2);
            *(float4*)&sEx[n * NC + jb] = e;
        }
#pragma unroll
        for (int h = 0; h < 2; h++) {
            float4 cv = *(const float4*)&sCood[i0 + (h << 2)];
            float4 e;
            e.x = __expf(-(y2 - ty * cv.x + cv.x * cv.x) * INV2S2);
            e.y = __expf(-(y2 - ty * cv.y + cv.y * cv.y) * INV2S2);
            e.z = __expf(-(y2 - ty * cv.z + cv.z * cv.z) * INV2S2);
            e.w = __expf(-(y2 - ty * cv.w + cv.w * cv.w) * INV2S2);
            *(float4*)&sEy0[n * 8 + (h << 2)] = e;

            float4 cw = *(const float4*)&sCood[i0 + 8 + (h << 2)];
            float4 f;
            f.x = __expf(-(y2 - ty * cw.x + cw.x * cw.x) * INV2S2);
            f.y = __expf(-(y2 - ty * cw.y + cw.y * cw.y) * INV2S2);
            f.z = __expf(-(y2 - ty * cw.z + cw.z * cw.z) * INV2S2);
            f.w = __expf(-(y2 - ty * cw.w + cw.w * cw.w) * INV2S2);
            *(float4*)&sEy1[n * 8 + (h << 2)] = f;
        }
    }
    __syncthreads();

    // ---- Phase A: tile0 reduce, 4-way n-split ----
    {
        int q  = t >> 6;                   // n quarter
        int r6 = t & 63;
        int ia = r6 >> 3;                  // i row 0..7
        int j8 = r6 & 7;                   // j octet

        const float4* exo = (const float4*)sEx + (j8 << 1);  // row = 16 float4

        float S[8], M[8];
#pragma unroll
        for (int k = 0; k < 8; k++) { S[k] = 0.f; M[k] = 0.f; }

        int n0 = q << 7;
#pragma unroll 4
        for (int nn = 0; nn < 128; nn++) {
            int n = n0 + nn;
            float  ey = sEy0[n * 8 + ia];
            float4 a  = exo[n * 16];
            float4 bq = exo[n * 16 + 1];
            float p0 = ey * a.x,  p1 = ey * a.y,  p2 = ey * a.z,  p3 = ey * a.w;
            float p4 = ey * bq.x, p5 = ey * bq.y, p6 = ey * bq.z, p7 = ey * bq.w;
            S[0] += p0; S[1] += p1; S[2] += p2; S[3] += p3;
            S[4] += p4; S[5] += p5; S[6] += p6; S[7] += p7;
            M[0] = fmaxf(M[0], p0); M[1] = fmaxf(M[1], p1);
            M[2] = fmaxf(M[2], p2); M[3] = fmaxf(M[3], p3);
            M[4] = fmaxf(M[4], p4); M[5] = fmaxf(M[5], p5);
            M[6] = fmaxf(M[6], p6); M[7] = fmaxf(M[7], p7);
        }
        int base = (q << 9) + (ia << 6) + (j8 << 3);
        *(float4*)&sPS[base]     = make_float4(S[0], S[1], S[2], S[3]);
        *(float4*)&sPS[base + 4] = make_float4(S[4], S[5], S[6], S[7]);
        *(float4*)&sPM[base]     = make_float4(M[0], M[1], M[2], M[3]);
        *(float4*)&sPM[base + 4] = make_float4(M[4], M[5], M[6], M[7]);
    }
    __syncthreads();

    // combine partials in (iloc, jp) layout
    float S0 = 0.f, S1 = 0.f, M0 = 0.f, M1 = 0.f;
    {
        int off = (iloc << 6) + (jp << 1);
#pragma unroll
        for (int q = 0; q < 4; q++) {
            float2 ps = *(const float2*)&sPS[(q << 9) + off];
            float2 pm = *(const float2*)&sPM[(q << 9) + off];
            S0 += ps.x; S1 += ps.y;
            M0 = fmaxf(M0, pm.x); M1 = fmaxf(M1, pm.y);
        }
    }

    float d = st_sizes[b] * BG_RATIO;

    float inv0x, inv0y;
    {
        float m0  = fmaxf(M0, 1e-35f);
        float m1  = fmaxf(M1, 1e-35f);
        float mn0 = fmaxf(-128.0f * __logf(m0), 0.0f);  // 2*sigma^2 = 128
        float mn1 = fmaxf(-128.0f * __logf(m1), 0.0f);
        float bd0 = d - sqrtf(mn0);
        float bd1 = d - sqrtf(mn1);
        float eb0 = __expf(-(bd0 * bd0) * INV2S2);
        float eb1 = __expf(-(bd1 * bd1) * INV2S2);
        inv0x = 1.0f / (S0 + eb0);
        inv0y = 1.0f / (S1 + eb1);
        float* bg = out + (size_t)b * ROWS * PIX + (size_t)NPTS * PIX
                        + (i0 + iloc) * NC + jp * 2;
        *(float2*)bg = make_float2(eb0 * inv0x, eb1 * inv0y);
    }

    const float2* exv = (const float2*)sEx + jp;   // row stride 32 float2
    float* outb  = out + (size_t)b * ROWS * PIX;
    float* orow0 = outb + (i0 + iloc) * NC + jp * 2;

    // ---- Phase B: store tile0 + reduce tile1 (shared ex load) ----
    float T0 = 0.f, T1 = 0.f, N0 = 0.f, N1 = 0.f;
#pragma unroll 4
    for (int n = 0; n < NPTS; n++) {
        float2 ex  = exv[n * 32];
        float  ey0 = sEy0[n * 8 + iloc];
        float  ey1 = sEy1[n * 8 + iloc];

        float2 o;
        o.x = ey0 * ex.x * inv0x;
        o.y = ey0 * ex.y * inv0y;
        *(float2*)(orow0 + (size_t)n * PIX) = o;

        float p0 = ey1 * ex.x, p1 = ey1 * ex.y;
        T0 += p0; T1 += p1;
        N0 = fmaxf(N0, p0); N1 = fmaxf(N1, p1);
    }

    // ---- finalize tile1 ----
    float inv1x, inv1y;
    {
        float m0  = fmaxf(N0, 1e-35f);
        float m1  = fmaxf(N1, 1e-35f);
        float mn0 = fmaxf(-128.0f * __logf(m0), 0.0f);
        float mn1 = fmaxf(-128.0f * __logf(m1), 0.0f);
        float bd0 = d - sqrtf(mn0);
        float bd1 = d - sqrtf(mn1);
        float eb0 = __expf(-(bd0 * bd0) * INV2S2);
        float eb1 = __expf(-(bd1 * bd1) * INV2S2);
        inv1x = 1.0f / (T0 + eb0);
        inv1y = 1.0f / (T1 + eb1);
        float* bg = outb + (size_t)NPTS * PIX + (i0 + 8 + iloc) * NC + jp * 2;
        *(float2*)bg = make_float2(eb0 * inv1x, eb1 * inv1y);
    }

    float* orow1 = outb + (i0 + 8 + iloc) * NC + jp * 2;

    // ---- Phase C: store tile1 ----
#pragma unroll 8
    for (int n = 0; n < NPTS; n++) {
        float2 ex  = exv[n * 32];
        float  ey1 = sEy1[n * 8 + iloc];
        float2 o;
        o.x = ey1 * ex.x * inv1x;
        o.y = ey1 * ex.y * inv1y;
        *(float2*)(orow1 + (size_t)n * PIX) = o;
    }
}

// ---------------------------------------------------------------------------
extern "C" void kernel_launch(void* const* d_in, const int* in_sizes, int n_in,
                              void* d_out, int out_size) {
    const float* points   = (const float*)d_in[0];
    const float* st_sizes = (const float*)d_in[1];
    const float* cood     = (const float*)d_in[2];
    float*       out      = (float*)d_out;

    cudaFuncSetAttribute(post_prob_kernel,
                         cudaFuncAttributeMaxDynamicSharedMemorySize,
                         SMEM_BYTES);

    post_prob_kernel<<<NB * 4, 256, SMEM_BYTES>>>(points, st_sizes, cood, out);
}

// round 13
// speedup vs baseline: 1.0298x; 1.0298x over previous
#include <cuda_runtime.h>

#define NB 32
#define NPTS 512
#define NC 64
#define PIX (NC * NC)          // 4096
#define ROWS (NPTS + 1)        // 513
#define INV2S2 0.0078125f      // 1/(2*8^2)
#define BG_RATIO 0.15f

// ---------------------------------------------------------------------------
// Single fused kernel. CTA = (batch b, chain c): tile0 = i rows [16c,16c+8),
// tile1 = [16c+8,16c+16). 256 threads: warp w = i-row, lane jp = j pair.
//
// Build: thread t computes rows n = t, t+256 of
//   sEx[n][j] = exp(-(x^2-2xc_j+c_j^2)/128)  (64 cols)
//   and TRANSPOSED Ey tiles sEy0T/sEy1T[i][n] (i = 8 rows per tile)
// directly from points[b] + cood. Transposed layout makes ey contiguous in n
// so the reduce loops load 4 n at a time with one broadcast LDS.128.
//
// A (exposed, DRAM idle -> minimized): tile0 reduce, 4-n unrolled.
// B: store tile0 row n AND accumulate tile1 (shared ex load) - reduce hidden.
// C: finalize tile1; store tile1 rows.
// Softmax identity: out = Ey*Ex/(S+ebg); bg = ebg/(S+ebg);
// min_dis = max(0, -128 ln(max_n Ey*Ex)). Exact quotient, no max-shift.
// ---------------------------------------------------------------------------
#define SMEM_BYTES ((NPTS * NC + NPTS * 16 + NC) * 4)   // 164096

__global__ __launch_bounds__(256, 1)
void post_prob_kernel(const float* __restrict__ points,
                      const float* __restrict__ st_sizes,
                      const float* __restrict__ cood,
                      float* __restrict__ out) {
    extern __shared__ float smem[];
    float* sEx    = smem;                   // [512][64]
    float* sEy0T  = smem + NPTS * NC;       // [8][512]  (transposed)
    float* sEy1T  = sEy0T + 8 * NPTS;       // [8][512]
    float* sCood  = sEy1T + 8 * NPTS;       // [64]

    int b  = blockIdx.x >> 2;
    int c  = blockIdx.x & 3;
    int i0 = c << 4;                        // tile0 base; tile1 = i0+8
    int t  = threadIdx.x;
    int iloc = t >> 5;                      // warp id (0..7) = row in tile
    int jp   = t & 31;                      // j pair index

    if (t < NC) sCood[t] = cood[t];
    __syncthreads();

    // ---- build phase ----
#pragma unroll
    for (int r = 0; r < 2; r++) {
        int n = t + (r << 8);
        float2 pt = *(const float2*)(points + ((size_t)b * NPTS + n) * 2);
        float x = pt.x, y = pt.y;
        float x2 = x * x, y2 = y * y;
        float tx = 2.0f * x, ty = 2.0f * y;

#pragma unroll
        for (int q = 0; q < 16; q++) {
            int jb = ((q + t) & 15) << 2;
            float4 cv = *(const float4*)&sCood[jb];
            float4 e;
            e.x = __expf(-(x2 - tx * cv.x + cv.x * cv.x) * INV2S2);
            e.y = __expf(-(x2 - tx * cv.y + cv.y * cv.y) * INV2S2);
            e.z = __expf(-(x2 - tx * cv.z + cv.z * cv.z) * INV2S2);
            e.w = __expf(-(x2 - tx * cv.w + cv.w * cv.w) * INV2S2);
            *(float4*)&sEx[n * NC + jb] = e;
        }
        // Transposed Ey tiles: scalar stores, stride-1 across lanes.
#pragma unroll
        for (int h = 0; h < 8; h++) {
            float cv = sCood[i0 + h];
            sEy0T[h * NPTS + n] = __expf(-(y2 - ty * cv + cv * cv) * INV2S2);
            float cw = sCood[i0 + 8 + h];
            sEy1T[h * NPTS + n] = __expf(-(y2 - ty * cw + cw * cw) * INV2S2);
        }
    }
    __syncthreads();

    const float2* exv  = (const float2*)sEx + jp;   // row stride 32 float2
    const float*  ey0T = sEy0T + iloc * NPTS;
    const float*  ey1T = sEy1T + iloc * NPTS;

    // ---- Phase A: tile0 reduce, 4-n unrolled, vectorized ey ----
    float S0 = 0.f, S1 = 0.f, M0 = 0.f, M1 = 0.f;
#pragma unroll 2
    for (int n4 = 0; n4 < NPTS; n4 += 4) {
        float4 ey = *(const float4*)(ey0T + n4);
        float2 e0 = exv[(n4 + 0) * 32];
        float2 e1 = exv[(n4 + 1) * 32];
        float2 e2 = exv[(n4 + 2) * 32];
        float2 e3 = exv[(n4 + 3) * 32];
        float p00 = ey.x * e0.x, p01 = ey.x * e0.y;
        float p10 = ey.y * e1.x, p11 = ey.y * e1.y;
        float p20 = ey.z * e2.x, p21 = ey.z * e2.y;
        float p30 = ey.w * e3.x, p31 = ey.w * e3.y;
        S0 += p00; S1 += p01;
        S0 += p10; S1 += p11;
        S0 += p20; S1 += p21;
        S0 += p30; S1 += p31;
        M0 = fmaxf(M0, p00); M1 = fmaxf(M1, p01);
        M0 = fmaxf(M0, p10); M1 = fmaxf(M1, p11);
        M0 = fmaxf(M0, p20); M1 = fmaxf(M1, p21);
        M0 = fmaxf(M0, p30); M1 = fmaxf(M1, p31);
    }

    float d = st_sizes[b] * BG_RATIO;

    float inv0x, inv0y;
    {
        float m0  = fmaxf(M0, 1e-35f);
        float m1  = fmaxf(M1, 1e-35f);
        float mn0 = fmaxf(-128.0f * __logf(m0), 0.0f);  // 2*sigma^2 = 128
        float mn1 = fmaxf(-128.0f * __logf(m1), 0.0f);
        float bd0 = d - sqrtf(mn0);
        float bd1 = d - sqrtf(mn1);
        float eb0 = __expf(-(bd0 * bd0) * INV2S2);
        float eb1 = __expf(-(bd1 * bd1) * INV2S2);
        inv0x = 1.0f / (S0 + eb0);
        inv0y = 1.0f / (S1 + eb1);
        float* bg = out + (size_t)b * ROWS * PIX + (size_t)NPTS * PIX
                        + (i0 + iloc) * NC + jp * 2;
        *(float2*)bg = make_float2(eb0 * inv0x, eb1 * inv0y);
    }

    float* outb  = out + (size_t)b * ROWS * PIX;
    float* orow0 = outb + (i0 + iloc) * NC + jp * 2;

    // ---- Phase B: store tile0 + reduce tile1 (shared ex load) ----
    float T0 = 0.f, T1 = 0.f, N0 = 0.f, N1 = 0.f;
    for (int n4 = 0; n4 < NPTS; n4 += 4) {
        float4 a0 = *(const float4*)(ey0T + n4);
        float4 a1 = *(const float4*)(ey1T + n4);
        const float* e0p = (const float*)&a0;
        const float* e1p = (const float*)&a1;
#pragma unroll
        for (int k = 0; k < 4; k++) {
            int n = n4 + k;
            float2 ex  = exv[n * 32];
            float  ey0 = e0p[k];
            float  ey1 = e1p[k];

            float2 o;
            o.x = ey0 * ex.x * inv0x;
            o.y = ey0 * ex.y * inv0y;
            *(float2*)(orow0 + (size_t)n * PIX) = o;

            float p0 = ey1 * ex.x, p1 = ey1 * ex.y;
            T0 += p0; T1 += p1;
            N0 = fmaxf(N0, p0); N1 = fmaxf(N1, p1);
        }
    }

    // ---- finalize tile1 ----
    float inv1x, inv1y;
    {
        float m0  = fmaxf(N0, 1e-35f);
        float m1  = fmaxf(N1, 1e-35f);
        float mn0 = fmaxf(-128.0f * __logf(m0), 0.0f);
        float mn1 = fmaxf(-128.0f * __logf(m1), 0.0f);
        float bd0 = d - sqrtf(mn0);
        float bd1 = d - sqrtf(mn1);
        float eb0 = __expf(-(bd0 * bd0) * INV2S2);
        float eb1 = __expf(-(bd1 * bd1) * INV2S2);
        inv1x = 1.0f / (T0 + eb0);
        inv1y = 1.0f / (T1 + eb1);
        float* bg = outb + (size_t)NPTS * PIX + (i0 + 8 + iloc) * NC + jp * 2;
        *(float2*)bg = make_float2(eb0 * inv1x, eb1 * inv1y);
    }

    float* orow1 = outb + (i0 + 8 + iloc) * NC + jp * 2;

    // ---- Phase C: store tile1 ----
    for (int n4 = 0; n4 < NPTS; n4 += 4) {
        float4 a1 = *(const float4*)(ey1T + n4);
        const float* e1p = (const float*)&a1;
#pragma unroll
        for (int k = 0; k < 4; k++) {
            int n = n4 + k;
            float2 ex  = exv[n * 32];
            float  ey1 = e1p[k];
            float2 o;
            o.x = ey1 * ex.x * inv1x;
            o.y = ey1 * ex.y * inv1y;
            *(float2*)(orow1 + (size_t)n * PIX) = o;
        }
    }
}

// ---------------------------------------------------------------------------
extern "C" void kernel_launch(void* const* d_in, const int* in_sizes, int n_in,
                              void* d_out, int out_size) {
    const float* points   = (const float*)d_in[0];
    const float* st_sizes = (const float*)d_in[1];
    const float* cood     = (const float*)d_in[2];
    float*       out      = (float*)d_out;

    cudaFuncSetAttribute(post_prob_kernel,
                         cudaFuncAttributeMaxDynamicSharedMemorySize,
                         SMEM_BYTES);

    post_prob_kernel<<<NB * 4, 256, SMEM_BYTES>>>(points, st_sizes, cood, out);
}